// round 14
// baseline (speedup 1.0000x reference)
#include <cuda_runtime.h>
#include <cuda_fp16.h>
#include <cstdint>

#define NN 4096
#define BB 4
#define C_IN 128
#define C_OUT 64
#define ICH 32                        // i-rows per colsumE block
#define RCHUNK (NN / ICH)             // 128 partial-sum chunks
#define ITILE 64
#define KCH 128                       // K elements per chunk
#define KSPLIT 2
#define KHALF (NN / KSPLIT)           // 2048
#define KCHUNKS (KHALF / KCH)         // 16 chunks per CTA
#define ESTR2 136                     // padded half-stride: 272B rows
#define TILEB (64 * ESTR2 * 2)        // 17408 bytes per tile
#define BUFB  (2 * TILEB)             // E + H = 34816
#define SMEM_DYN (2 * BUFB)           // 69632 (2-stage; 3 CTAs/SM)

// ---------------- scratch -----------------------------------------------------
__device__ float    g_h  [BB * NN * C_OUT];
__device__ float    g_f1 [BB * NN];          // 0.5 * own-type k score
__device__ float    g_f2 [BB * NN];          // 0.5 * own-type v score
__device__ float    g_Sp [RCHUNK * BB * NN];
__device__ uint16_t g_hT [BB * 64 * NN];     // fp16 (h*rS)^T, [b][o][j]
__device__ uint16_t g_E  [(size_t)BB * NN * NN];  // fp16 unnormalized E, [b][i][j]
__device__ float    g_P  [KSPLIT][BB * NN * C_OUT];  // split-K partials

// ---------------- helpers ------------------------------------------------------
__device__ __forceinline__ uint32_t smem_u32(const void* p) {
    uint32_t a;
    asm("{ .reg .u64 t; cvta.to.shared.u64 t, %1; cvt.u32.u64 %0, t; }" : "=r"(a) : "l"(p));
    return a;
}
__device__ __forceinline__ uint32_t pack_f16(float lo, float hi) {
    uint32_t r;
    asm("cvt.rn.f16x2.f32 %0, %1, %2;" : "=r"(r) : "f"(hi), "f"(lo));
    return r;
}
__device__ __forceinline__ void cp16(uint32_t dst, const void* src) {
    asm volatile("cp.async.cg.shared.global [%0], [%1], 16;" :: "r"(dst), "l"(src) : "memory");
}
__device__ __forceinline__ void ldsm4(uint32_t* r, uint32_t addr) {
    asm volatile("ldmatrix.sync.aligned.m8n8.x4.shared.b16 {%0,%1,%2,%3}, [%4];"
        : "=r"(r[0]), "=r"(r[1]), "=r"(r[2]), "=r"(r[3]) : "r"(addr));
}
__device__ __forceinline__ void mma16816(float* c, const uint32_t* a, uint32_t b0, uint32_t b1) {
    asm volatile("mma.sync.aligned.m16n8k16.row.col.f32.f16.f16.f32 "
        "{%0,%1,%2,%3}, {%4,%5,%6,%7}, {%8,%9}, {%0,%1,%2,%3};"
        : "+f"(c[0]), "+f"(c[1]), "+f"(c[2]), "+f"(c[3])
        : "r"(a[0]), "r"(a[1]), "r"(a[2]), "r"(a[3]), "r"(b0), "r"(b1));
}

// E = exp(sigmoid(x)-0.5); f pre-halved: t = tanh(x/2), E = exp(t/2) deg-5 Horner.
__device__ __forceinline__ float e_of(float a, float f12h) {
    float xh = a * f12h, t;
    asm("tanh.approx.f32 %0, %1;" : "=f"(t) : "f"(xh));
    float p = fmaf(t, 2.604166667e-4f, 2.604166667e-3f);
    p = fmaf(p, t, 2.083333333e-2f);
    p = fmaf(p, t, 0.125f);
    p = fmaf(p, t, 0.5f);
    p = fmaf(p, t, 1.0f);
    return p;
}

// ---------------- kernel 1: proj (float4 LDS) + fused gate scalars --------------
__global__ __launch_bounds__(256) void k_proj(const float* __restrict__ node_rep,
                                              const float* __restrict__ proj_W,
                                              const float* __restrict__ proj_b,
                                              const int*   __restrict__ node_type,
                                              const float* __restrict__ k_W,
                                              const float* __restrict__ k_b,
                                              const float* __restrict__ v_W,
                                              const float* __restrict__ v_b) {
    __shared__ __align__(16) float pw[C_OUT][C_IN + 4];
    __shared__ __align__(16) float nr[16][C_IN];
    __shared__ float hs[16][C_OUT + 1];
    int tid = threadIdx.x;
    for (int k = tid; k < C_OUT * C_IN; k += 256)
        pw[k / C_IN][k % C_IN] = proj_W[k];
    int row0 = blockIdx.x * 16;
    for (int k = tid; k < 16 * C_IN; k += 256)
        nr[k / C_IN][k % C_IN] = node_rep[(row0 + k / C_IN) * C_IN + (k % C_IN)];
    __syncthreads();
    int o  = tid & 63;
    int rg = tid >> 6;
    float bias = proj_b[o];
    const float4* pw4 = (const float4*)&pw[o][0];
    #pragma unroll
    for (int rr = 0; rr < 4; rr++) {
        int r = rg * 4 + rr;
        const float4* nr4 = (const float4*)&nr[r][0];
        float acc = 0.0f;
        #pragma unroll 8
        for (int c4 = 0; c4 < C_IN / 4; c4++) {
            float4 a = nr4[c4], w = pw4[c4];
            acc += a.x * w.x + a.y * w.y + a.z * w.z + a.w * w.w;
        }
        acc += bias;
        g_h[(row0 + r) * C_OUT + o] = acc;
        hs[r][o] = acc;
    }
    __syncthreads();

    int warp = tid >> 5, lane = tid & 31;
    #pragma unroll
    for (int rr = 0; rr < 2; rr++) {
        int r = warp * 2 + rr;
        int grow = row0 + r;
        int t = node_type[grow & (NN - 1)];
        float h0 = hs[r][lane], h1 = hs[r][lane + 32];
        float p1 = h0 * k_W[t * 64 + lane] + h1 * k_W[t * 64 + lane + 32];
        float p2 = h0 * v_W[t * 64 + lane] + h1 * v_W[t * 64 + lane + 32];
        #pragma unroll
        for (int off = 16; off; off >>= 1) {
            p1 += __shfl_down_sync(0xffffffffu, p1, off);
            p2 += __shfl_down_sync(0xffffffffu, p2, off);
        }
        if (lane == 0) {
            g_f1[grow] = 0.5f * (p1 + k_b[t]);
            g_f2[grow] = 0.5f * (p2 + v_b[t]);
        }
    }
}

// ---------------- kernel 2: column sums + materialize E fp16 -------------------
__global__ __launch_bounds__(128) void k_colsumE(const float* __restrict__ adj) {
    __shared__ float f1s[BB][ICH];
    int tid = threadIdx.x;
    int j0 = blockIdx.x * 512 + tid * 4;
    int i0 = blockIdx.y * ICH;

    if (tid < BB * ICH) {
        int b = tid / ICH, ii = tid % ICH;
        f1s[b][ii] = g_f1[b * NN + i0 + ii];
    }
    __syncthreads();

    float4 f2v[BB], s[BB];
    #pragma unroll
    for (int b = 0; b < BB; b++) {
        f2v[b] = *(const float4*)(g_f2 + b * NN + j0);
        s[b] = make_float4(0.f, 0.f, 0.f, 0.f);
    }

    for (int ii = 0; ii < ICH; ii++) {
        int i = i0 + ii;
        float4 a = *(const float4*)(adj + (size_t)i * NN + j0);
        #pragma unroll
        for (int b = 0; b < BB; b++) {
            float f1 = f1s[b][ii];
            float e0 = e_of(a.x, f1 + f2v[b].x);
            float e1 = e_of(a.y, f1 + f2v[b].y);
            float e2 = e_of(a.z, f1 + f2v[b].z);
            float e3 = e_of(a.w, f1 + f2v[b].w);
            s[b].x += e0; s[b].y += e1; s[b].z += e2; s[b].w += e3;
            *(uint2*)&g_E[((size_t)b * NN + i) * NN + j0] =
                make_uint2(pack_f16(e0, e1), pack_f16(e2, e3));
        }
    }
    #pragma unroll
    for (int b = 0; b < BB; b++)
        *(float4*)&g_Sp[(size_t)(blockIdx.y * BB + b) * NN + j0] = s[b];
}

// ---------------- kernel 3: fused rS + transpose -> fp16 hT ---------------------
__global__ __launch_bounds__(256) void k_finalize() {
    __shared__ float red[4][64];
    __shared__ float rSs[64];
    __shared__ float ts[64][65];
    int b = blockIdx.y, j0 = blockIdx.x * 64;
    int tid = threadIdx.x;

    {
        int j = tid & 63, seg = tid >> 6;
        float s = 0.0f;
        #pragma unroll 8
        for (int k = 0; k < RCHUNK / 4; k++) {
            int rc = seg * (RCHUNK / 4) + k;
            s += g_Sp[(size_t)(rc * BB + b) * NN + j0 + j];
        }
        red[seg][j] = s;
    }
    __syncthreads();
    if (tid < 64)
        rSs[tid] = __fdividef(4096.0f, red[0][tid] + red[1][tid] + red[2][tid] + red[3][tid]);
    __syncthreads();

    #pragma unroll
    for (int k = tid; k < 64 * 64; k += 256) {
        int jj = k >> 6, o = k & 63;
        ts[jj][o] = g_h[((size_t)(b * NN + j0 + jj)) * 64 + o] * rSs[jj];
    }
    __syncthreads();
    int o = tid >> 2, seg = tid & 3;
    uint32_t* dst = (uint32_t*)&g_hT[((size_t)b * 64 + o) * NN + j0 + seg * 16];
    #pragma unroll
    for (int q = 0; q < 8; q++) {
        int j = seg * 16 + q * 2;
        dst[q] = pack_f16(ts[j][o], ts[j + 1][o]);
    }
}

// ---------------- kernel 4: fp16 GEMM, split-K=2, 2-stage cp.async --------------
__global__ __launch_bounds__(256)
void k_main_mma() {
    extern __shared__ __align__(16) char dyn[];

    int tid  = threadIdx.x;
    int wid  = tid >> 5;
    int lane = tid & 31;
    int it = blockIdx.x, b = blockIdx.y, kz = blockIdx.z;
    int i0 = it * ITILE;

    int mw = wid & 3;
    int nw = wid >> 2;

    uint32_t base = smem_u32(dyn);
    uint32_t eA[2] = { base,         base + BUFB };
    uint32_t hB[2] = { base + TILEB, base + BUFB + TILEB };

    int srow = tid >> 4;
    int sseg = tid & 15;
    const uint16_t* esrc0 = &g_E[((size_t)b * NN + i0) * NN + (size_t)kz * KHALF];
    const uint16_t* hsrc0 = &g_hT[(size_t)b * 64 * NN + (size_t)kz * KHALF];

    float acc[4][4];
    #pragma unroll
    for (int nt = 0; nt < 4; nt++)
        #pragma unroll
        for (int q = 0; q < 4; q++) acc[nt][q] = 0.0f;

    // prologue: stage chunk 0 into buf 0
    #pragma unroll
    for (int k2 = 0; k2 < 4; k2++) {
        int row = srow + 16 * k2;
        cp16(eA[0] + (uint32_t)(row * (ESTR2 * 2) + sseg * 16),
             esrc0 + (size_t)row * NN + sseg * 8);
        cp16(hB[0] + (uint32_t)(row * (ESTR2 * 2) + sseg * 16),
             hsrc0 + (size_t)row * NN + sseg * 8);
    }
    asm volatile("cp.async.commit_group;" ::: "memory");

    int rowl = lane & 15;
    int koff = 8 * (lane >> 4);
    uint32_t aBase = (uint32_t)(((mw * 16 + rowl) * ESTR2 + koff) * 2);
    uint32_t bBase0 = (uint32_t)(((nw * 32 + rowl) * ESTR2 + koff) * 2);
    uint32_t bBase1 = (uint32_t)(((nw * 32 + 16 + rowl) * ESTR2 + koff) * 2);

    for (int c = 0; c < KCHUNKS; c++) {
        int buf = c & 1;

        asm volatile("cp.async.wait_group 0;" ::: "memory");
        __syncthreads();   // buf c ready AND all warps finished MMA(c-1)

        if (c + 1 < KCHUNKS) {
            int nb = buf ^ 1;
            #pragma unroll
            for (int k2 = 0; k2 < 4; k2++) {
                int row = srow + 16 * k2;
                cp16(eA[nb] + (uint32_t)(row * (ESTR2 * 2) + sseg * 16),
                     esrc0 + (size_t)row * NN + (c + 1) * KCH + sseg * 8);
                cp16(hB[nb] + (uint32_t)(row * (ESTR2 * 2) + sseg * 16),
                     hsrc0 + (size_t)row * NN + (c + 1) * KCH + sseg * 8);
            }
            asm volatile("cp.async.commit_group;" ::: "memory");
        }

        uint32_t af[2][4], bf0[2][4], bf1[2][4];
        ldsm4(af[0],  eA[buf] + aBase);
        ldsm4(bf0[0], hB[buf] + bBase0);
        ldsm4(bf1[0], hB[buf] + bBase1);
        #pragma unroll
        for (int ks = 0; ks < 8; ks++) {
            int cur = ks & 1, nxt = cur ^ 1;
            if (ks < 7) {
                uint32_t kadd = (uint32_t)((ks + 1) * 16 * 2);
                ldsm4(af[nxt],  eA[buf] + aBase  + kadd);
                ldsm4(bf0[nxt], hB[buf] + bBase0 + kadd);
                ldsm4(bf1[nxt], hB[buf] + bBase1 + kadd);
            }
            mma16816(acc[0], af[cur], bf0[cur][0], bf0[cur][2]);
            mma16816(acc[1], af[cur], bf0[cur][1], bf0[cur][3]);
            mma16816(acc[2], af[cur], bf1[cur][0], bf1[cur][2]);
            mma16816(acc[3], af[cur], bf1[cur][1], bf1[cur][3]);
        }
    }

    // epilogue: write split-K partial (scale folded here; exact pow2)
    const float sc = 1.0f / 4096.0f;
    float* pout = g_P[kz];
    int rr = lane >> 2;
    int cc = (lane & 3) * 2;
    #pragma unroll
    for (int nt = 0; nt < 4; nt++) {
        size_t row = (size_t)b * NN + i0 + mw * 16 + rr;
        int col = nw * 32 + nt * 8 + cc;
        *(float2*)(pout + row * 64 + col) =
            make_float2(acc[nt][0] * sc, acc[nt][1] * sc);
        *(float2*)(pout + (row + 8) * 64 + col) =
            make_float2(acc[nt][2] * sc, acc[nt][3] * sc);
    }
}

// ---------------- kernel 5: out = P0 + P1 ---------------------------------------
__global__ __launch_bounds__(256) void k_add(float* __restrict__ out) {
    int idx = blockIdx.x * 256 + threadIdx.x;   // over BB*NN*64/4 float4s
    float4 a = ((const float4*)g_P[0])[idx];
    float4 b = ((const float4*)g_P[1])[idx];
    ((float4*)out)[idx] = make_float4(a.x + b.x, a.y + b.y, a.z + b.z, a.w + b.w);
}

// ---------------- launch ---------------------------------------------------------
extern "C" void kernel_launch(void* const* d_in, const int* in_sizes, int n_in,
                              void* d_out, int out_size) {
    const float* node_rep = (const float*)d_in[0];
    const float* adj      = (const float*)d_in[1];
    const int*   node_ty  = (const int*)  d_in[2];
    const float* proj_W   = (const float*)d_in[3];
    const float* proj_b   = (const float*)d_in[4];
    const float* k_W      = (const float*)d_in[5];
    const float* k_b      = (const float*)d_in[6];
    const float* v_W      = (const float*)d_in[7];
    const float* v_b      = (const float*)d_in[8];
    float* out = (float*)d_out;

    static bool attr_done = false;
    if (!attr_done) {
        cudaFuncSetAttribute(k_main_mma, cudaFuncAttributeMaxDynamicSharedMemorySize, SMEM_DYN);
        attr_done = true;
    }

    k_proj    <<<(BB * NN) / 16, 256>>>(node_rep, proj_W, proj_b,
                                        node_ty, k_W, k_b, v_W, v_b);
    k_colsumE <<<dim3(NN / 512, NN / ICH), 128>>>(adj);
    k_finalize<<<dim3(NN / 64, BB), 256>>>();
    k_main_mma<<<dim3(NN / ITILE, BB, KSPLIT), 256, SMEM_DYN>>>();
    k_add     <<<(BB * NN * C_OUT / 4) / 256, 256>>>(out);
}

// round 15
// speedup vs baseline: 1.0437x; 1.0437x over previous
#include <cuda_runtime.h>
#include <cuda_fp16.h>
#include <cstdint>

#define NN 4096
#define BB 4
#define C_IN 128
#define C_OUT 64
#define ICH 32                        // i-rows per colsumE block
#define RCHUNK (NN / ICH)             // 128 partial-sum chunks
#define ITILE 64
#define KCH 128                       // K elements per chunk
#define CHUNKS (NN / KCH)             // 32
#define ESTR2 136                     // padded half-stride: 272B rows
#define TILEB (64 * ESTR2 * 2)        // 17408 bytes per tile
#define BUFB  (2 * TILEB)             // E + H = 34816
#define SMEM_DYN (2 * BUFB)           // 69632 (2-stage; 3 CTAs/SM)

// ---------------- scratch -----------------------------------------------------
__device__ float    g_h  [BB * NN * C_OUT];
__device__ float    g_f1 [BB * NN];          // 0.5 * own-type k score
__device__ float    g_f2 [BB * NN];          // 0.5 * own-type v score
__device__ float    g_Sp [RCHUNK * BB * NN];
__device__ uint16_t g_hT [BB * 64 * NN];     // fp16 (h*rS)^T, [b][o][j]
__device__ uint16_t g_E  [(size_t)BB * NN * NN];  // fp16 unnormalized E, [b][i][j]

// ---------------- helpers ------------------------------------------------------
__device__ __forceinline__ uint32_t smem_u32(const void* p) {
    uint32_t a;
    asm("{ .reg .u64 t; cvta.to.shared.u64 t, %1; cvt.u32.u64 %0, t; }" : "=r"(a) : "l"(p));
    return a;
}
__device__ __forceinline__ uint32_t pack_f16(float lo, float hi) {
    uint32_t r;
    asm("cvt.rn.f16x2.f32 %0, %1, %2;" : "=r"(r) : "f"(hi), "f"(lo));
    return r;
}
__device__ __forceinline__ void cp16(uint32_t dst, const void* src) {
    asm volatile("cp.async.cg.shared.global [%0], [%1], 16;" :: "r"(dst), "l"(src) : "memory");
}
__device__ __forceinline__ void ldsm4(uint32_t* r, uint32_t addr) {
    asm volatile("ldmatrix.sync.aligned.m8n8.x4.shared.b16 {%0,%1,%2,%3}, [%4];"
        : "=r"(r[0]), "=r"(r[1]), "=r"(r[2]), "=r"(r[3]) : "r"(addr));
}
__device__ __forceinline__ void mma16816(float* c, const uint32_t* a, uint32_t b0, uint32_t b1) {
    asm volatile("mma.sync.aligned.m16n8k16.row.col.f32.f16.f16.f32 "
        "{%0,%1,%2,%3}, {%4,%5,%6,%7}, {%8,%9}, {%0,%1,%2,%3};"
        : "+f"(c[0]), "+f"(c[1]), "+f"(c[2]), "+f"(c[3])
        : "r"(a[0]), "r"(a[1]), "r"(a[2]), "r"(a[3]), "r"(b0), "r"(b1));
}

// E = exp(sigmoid(x)-0.5); f pre-halved: t = tanh(x/2), E = exp(t/2) deg-5 Horner.
__device__ __forceinline__ float e_of(float a, float f12h) {
    float xh = a * f12h, t;
    asm("tanh.approx.f32 %0, %1;" : "=f"(t) : "f"(xh));
    float p = fmaf(t, 2.604166667e-4f, 2.604166667e-3f);
    p = fmaf(p, t, 2.083333333e-2f);
    p = fmaf(p, t, 0.125f);
    p = fmaf(p, t, 0.5f);
    p = fmaf(p, t, 1.0f);
    return p;
}

// ---------------- kernel 1: proj (float4 LDS) + fused gate scalars --------------
__global__ __launch_bounds__(256) void k_proj(const float* __restrict__ node_rep,
                                              const float* __restrict__ proj_W,
                                              const float* __restrict__ proj_b,
                                              const int*   __restrict__ node_type,
                                              const float* __restrict__ k_W,
                                              const float* __restrict__ k_b,
                                              const float* __restrict__ v_W,
                                              const float* __restrict__ v_b) {
    __shared__ __align__(16) float pw[C_OUT][C_IN + 4];
    __shared__ __align__(16) float nr[16][C_IN];
    __shared__ float hs[16][C_OUT + 1];
    int tid = threadIdx.x;
    for (int k = tid; k < C_OUT * C_IN; k += 256)
        pw[k / C_IN][k % C_IN] = proj_W[k];
    int row0 = blockIdx.x * 16;
    for (int k = tid; k < 16 * C_IN; k += 256)
        nr[k / C_IN][k % C_IN] = node_rep[(row0 + k / C_IN) * C_IN + (k % C_IN)];
    __syncthreads();
    int o  = tid & 63;
    int rg = tid >> 6;
    float bias = proj_b[o];
    const float4* pw4 = (const float4*)&pw[o][0];
    #pragma unroll
    for (int rr = 0; rr < 4; rr++) {
        int r = rg * 4 + rr;
        const float4* nr4 = (const float4*)&nr[r][0];
        float acc = 0.0f;
        #pragma unroll 8
        for (int c4 = 0; c4 < C_IN / 4; c4++) {
            float4 a = nr4[c4], w = pw4[c4];
            acc += a.x * w.x + a.y * w.y + a.z * w.z + a.w * w.w;
        }
        acc += bias;
        g_h[(row0 + r) * C_OUT + o] = acc;
        hs[r][o] = acc;
    }
    __syncthreads();

    int warp = tid >> 5, lane = tid & 31;
    #pragma unroll
    for (int rr = 0; rr < 2; rr++) {
        int r = warp * 2 + rr;
        int grow = row0 + r;
        int t = node_type[grow & (NN - 1)];
        float h0 = hs[r][lane], h1 = hs[r][lane + 32];
        float p1 = h0 * k_W[t * 64 + lane] + h1 * k_W[t * 64 + lane + 32];
        float p2 = h0 * v_W[t * 64 + lane] + h1 * v_W[t * 64 + lane + 32];
        #pragma unroll
        for (int off = 16; off; off >>= 1) {
            p1 += __shfl_down_sync(0xffffffffu, p1, off);
            p2 += __shfl_down_sync(0xffffffffu, p2, off);
        }
        if (lane == 0) {
            g_f1[grow] = 0.5f * (p1 + k_b[t]);
            g_f2[grow] = 0.5f * (p2 + v_b[t]);
        }
    }
}

// ---------------- kernel 2: column sums + materialize E fp16 -------------------
// grid (NN/1024, NN/ICH); 256 threads; 4 j x 4 b per thread; ii unrolled x2 (MLP=2).
__global__ __launch_bounds__(256) void k_colsumE(const float* __restrict__ adj) {
    __shared__ float f1s[BB][ICH];
    int tid = threadIdx.x;
    int j0 = blockIdx.x * 1024 + tid * 4;
    int i0 = blockIdx.y * ICH;

    if (tid < BB * ICH) {
        int b = tid / ICH, ii = tid % ICH;
        f1s[b][ii] = g_f1[b * NN + i0 + ii];
    }
    __syncthreads();

    float4 f2v[BB], s[BB];
    #pragma unroll
    for (int b = 0; b < BB; b++) {
        f2v[b] = *(const float4*)(g_f2 + b * NN + j0);
        s[b] = make_float4(0.f, 0.f, 0.f, 0.f);
    }

    for (int ii = 0; ii < ICH; ii += 2) {
        int i = i0 + ii;
        // both adj rows in flight before any compute (MLP=2, evict-first)
        float4 a0 = __ldcs((const float4*)(adj + (size_t)i * NN + j0));
        float4 a1 = __ldcs((const float4*)(adj + (size_t)(i + 1) * NN + j0));
        #pragma unroll
        for (int b = 0; b < BB; b++) {
            float f1 = f1s[b][ii];
            float e0 = e_of(a0.x, f1 + f2v[b].x);
            float e1 = e_of(a0.y, f1 + f2v[b].y);
            float e2 = e_of(a0.z, f1 + f2v[b].z);
            float e3 = e_of(a0.w, f1 + f2v[b].w);
            s[b].x += e0; s[b].y += e1; s[b].z += e2; s[b].w += e3;
            __stcs((uint2*)&g_E[((size_t)b * NN + i) * NN + j0],
                   make_uint2(pack_f16(e0, e1), pack_f16(e2, e3)));
        }
        #pragma unroll
        for (int b = 0; b < BB; b++) {
            float f1 = f1s[b][ii + 1];
            float e0 = e_of(a1.x, f1 + f2v[b].x);
            float e1 = e_of(a1.y, f1 + f2v[b].y);
            float e2 = e_of(a1.z, f1 + f2v[b].z);
            float e3 = e_of(a1.w, f1 + f2v[b].w);
            s[b].x += e0; s[b].y += e1; s[b].z += e2; s[b].w += e3;
            __stcs((uint2*)&g_E[((size_t)b * NN + i + 1) * NN + j0],
                   make_uint2(pack_f16(e0, e1), pack_f16(e2, e3)));
        }
    }
    #pragma unroll
    for (int b = 0; b < BB; b++)
        __stcs((float4*)&g_Sp[(size_t)(blockIdx.y * BB + b) * NN + j0], s[b]);
}

// ---------------- kernel 3: fused rS + transpose -> fp16 hT ---------------------
__global__ __launch_bounds__(256) void k_finalize() {
    __shared__ float red[4][64];
    __shared__ float rSs[64];
    __shared__ float ts[64][65];
    int b = blockIdx.y, j0 = blockIdx.x * 64;
    int tid = threadIdx.x;

    {
        int j = tid & 63, seg = tid >> 6;
        float s = 0.0f;
        #pragma unroll 8
        for (int k = 0; k < RCHUNK / 4; k++) {
            int rc = seg * (RCHUNK / 4) + k;
            s += g_Sp[(size_t)(rc * BB + b) * NN + j0 + j];
        }
        red[seg][j] = s;
    }
    __syncthreads();
    if (tid < 64)
        rSs[tid] = __fdividef(4096.0f, red[0][tid] + red[1][tid] + red[2][tid] + red[3][tid]);
    __syncthreads();

    #pragma unroll
    for (int k = tid; k < 64 * 64; k += 256) {
        int jj = k >> 6, o = k & 63;
        ts[jj][o] = g_h[((size_t)(b * NN + j0 + jj)) * 64 + o] * rSs[jj];
    }
    __syncthreads();
    int o = tid >> 2, seg = tid & 3;
    uint32_t* dst = (uint32_t*)&g_hT[((size_t)b * 64 + o) * NN + j0 + seg * 16];
    #pragma unroll
    for (int q = 0; q < 8; q++) {
        int j = seg * 16 + q * 2;
        dst[q] = pack_f16(ts[j][o], ts[j + 1][o]);
    }
}

// ---------------- kernel 4: fp16 GEMM, 2-stage cp.async (R12-proven) -----------
__global__ __launch_bounds__(256)
void k_main_mma(float* __restrict__ out) {
    extern __shared__ __align__(16) char dyn[];

    int tid  = threadIdx.x;
    int wid  = tid >> 5;
    int lane = tid & 31;
    int it = blockIdx.x, b = blockIdx.y;
    int i0 = it * ITILE;

    int mw = wid & 3;
    int nw = wid >> 2;

    uint32_t base = smem_u32(dyn);
    uint32_t eA[2] = { base,         base + BUFB };
    uint32_t hB[2] = { base + TILEB, base + BUFB + TILEB };

    int srow = tid >> 4;
    int sseg = tid & 15;
    const uint16_t* esrc0 = &g_E[((size_t)b * NN + i0) * NN];
    const uint16_t* hsrc0 = &g_hT[(size_t)b * 64 * NN];

    float acc[4][4];
    #pragma unroll
    for (int nt = 0; nt < 4; nt++)
        #pragma unroll
        for (int q = 0; q < 4; q++) acc[nt][q] = 0.0f;

    #pragma unroll
    for (int k2 = 0; k2 < 4; k2++) {
        int row = srow + 16 * k2;
        cp16(eA[0] + (uint32_t)(row * (ESTR2 * 2) + sseg * 16),
             esrc0 + (size_t)row * NN + sseg * 8);
        cp16(hB[0] + (uint32_t)(row * (ESTR2 * 2) + sseg * 16),
             hsrc0 + (size_t)row * NN + sseg * 8);
    }
    asm volatile("cp.async.commit_group;" ::: "memory");

    int rowl = lane & 15;
    int koff = 8 * (lane >> 4);
    uint32_t aBase = (uint32_t)(((mw * 16 + rowl) * ESTR2 + koff) * 2);
    uint32_t bBase0 = (uint32_t)(((nw * 32 + rowl) * ESTR2 + koff) * 2);
    uint32_t bBase1 = (uint32_t)(((nw * 32 + 16 + rowl) * ESTR2 + koff) * 2);

    for (int c = 0; c < CHUNKS; c++) {
        int buf = c & 1;

        asm volatile("cp.async.wait_group 0;" ::: "memory");
        __syncthreads();   // buf c ready AND all warps finished MMA(c-1)

        if (c + 1 < CHUNKS) {
            int nb = buf ^ 1;
            #pragma unroll
            for (int k2 = 0; k2 < 4; k2++) {
                int row = srow + 16 * k2;
                cp16(eA[nb] + (uint32_t)(row * (ESTR2 * 2) + sseg * 16),
                     esrc0 + (size_t)row * NN + (c + 1) * KCH + sseg * 8);
                cp16(hB[nb] + (uint32_t)(row * (ESTR2 * 2) + sseg * 16),
                     hsrc0 + (size_t)row * NN + (c + 1) * KCH + sseg * 8);
            }
            asm volatile("cp.async.commit_group;" ::: "memory");
        }

        uint32_t af[2][4], bf0[2][4], bf1[2][4];
        ldsm4(af[0],  eA[buf] + aBase);
        ldsm4(bf0[0], hB[buf] + bBase0);
        ldsm4(bf1[0], hB[buf] + bBase1);
        #pragma unroll
        for (int ks = 0; ks < 8; ks++) {
            int cur = ks & 1, nxt = cur ^ 1;
            if (ks < 7) {
                uint32_t kadd = (uint32_t)((ks + 1) * 16 * 2);
                ldsm4(af[nxt],  eA[buf] + aBase  + kadd);
                ldsm4(bf0[nxt], hB[buf] + bBase0 + kadd);
                ldsm4(bf1[nxt], hB[buf] + bBase1 + kadd);
            }
            mma16816(acc[0], af[cur], bf0[cur][0], bf0[cur][2]);
            mma16816(acc[1], af[cur], bf0[cur][1], bf0[cur][3]);
            mma16816(acc[2], af[cur], bf1[cur][0], bf1[cur][2]);
            mma16816(acc[3], af[cur], bf1[cur][1], bf1[cur][3]);
        }
    }

    const float sc = 1.0f / 4096.0f;
    int rr = lane >> 2;
    int cc = (lane & 3) * 2;
    #pragma unroll
    for (int nt = 0; nt < 4; nt++) {
        size_t row = (size_t)b * NN + i0 + mw * 16 + rr;
        int col = nw * 32 + nt * 8 + cc;
        *(float2*)(out + row * 64 + col) =
            make_float2(acc[nt][0] * sc, acc[nt][1] * sc);
        *(float2*)(out + (row + 8) * 64 + col) =
            make_float2(acc[nt][2] * sc, acc[nt][3] * sc);
    }
}

// ---------------- launch ---------------------------------------------------------
extern "C" void kernel_launch(void* const* d_in, const int* in_sizes, int n_in,
                              void* d_out, int out_size) {
    const float* node_rep = (const float*)d_in[0];
    const float* adj      = (const float*)d_in[1];
    const int*   node_ty  = (const int*)  d_in[2];
    const float* proj_W   = (const float*)d_in[3];
    const float* proj_b   = (const float*)d_in[4];
    const float* k_W      = (const float*)d_in[5];
    const float* k_b      = (const float*)d_in[6];
    const float* v_W      = (const float*)d_in[7];
    const float* v_b      = (const float*)d_in[8];
    float* out = (float*)d_out;

    static bool attr_done = false;
    if (!attr_done) {
        cudaFuncSetAttribute(k_main_mma, cudaFuncAttributeMaxDynamicSharedMemorySize, SMEM_DYN);
        attr_done = true;
    }

    k_proj    <<<(BB * NN) / 16, 256>>>(node_rep, proj_W, proj_b,
                                        node_ty, k_W, k_b, v_W, v_b);
    k_colsumE <<<dim3(NN / 1024, NN / ICH), 256>>>(adj);
    k_finalize<<<dim3(NN / 64, BB), 256>>>();
    k_main_mma<<<dim3(NN / ITILE, BB), 256, SMEM_DYN>>>(out);
}